// round 11
// baseline (speedup 1.0000x reference)
#include <cuda_runtime.h>
#include <cuda_fp16.h>

// PatternDetector: B=131072 rows x L=256 int32 in [0,40). Output Bx4 f32.
//
// Stable "nonzeros-first" argsort preserves order -> all features are
// functions of consecutive-nonzero pairs -> forward scan per row.
// dec = (n-1) - rep - inc.
//
// R11: warp-per-row, no shared memory, no barriers.
// Lane l holds elements [4l,4l+4) (chunk A) and [128+4l,128+4l+4) (chunk B).
// Both warp-wide LDG.128 are 512B-contiguous (perfect coalescing).
// Scan = proven SWAR half2 loop (values as half 1024+v = bits 0x6400|v;
// compares -> 0xFFFF masks via set.*.u32.f16x2; prev blends = 1 LOP3;
// counters packed u16x2 via vsub2) over only 4 steps per lane.
// Chain inits come from the neighbor lane's packed word via shfl (>=2
// nonzeros in 4 elements w.p. 1-6e-5; rare fallback walks gmem).
// Reduction: 4x REDUX (__reduce_add_sync); lane sums <=128 per u16, safe.

constexpr int L_LEN = 256;
constexpr int TPB   = 256;     // 8 warps = 8 rows per block

__device__ __forceinline__ unsigned heq2_mask(unsigned a, unsigned b) {
    unsigned d; asm("set.eq.u32.f16x2 %0, %1, %2;" : "=r"(d) : "r"(a), "r"(b)); return d;
}
__device__ __forceinline__ unsigned hgt2_mask(unsigned a, unsigned b) {
    unsigned d; asm("set.gt.u32.f16x2 %0, %1, %2;" : "=r"(d) : "r"(a), "r"(b)); return d;
}
__device__ __forceinline__ unsigned hne2_mask(unsigned a, unsigned b) {
    unsigned d; asm("set.ne.u32.f16x2 %0, %1, %2;" : "=r"(d) : "r"(a), "r"(b)); return d;
}

// branchless "last two nonzeros" of a 4-byte word (ascending position order)
__device__ __forceinline__ void last2nz_word(unsigned w, int& p1, int& p2, int& cnt)
{
    p1 = 0; p2 = 0; cnt = 0;
    #pragma unroll
    for (int k = 0; k < 4; ++k) {
        int v = (w >> (8 * k)) & 0xff;
        bool nz = (v != 0);
        p2 = nz ? p1 : p2;
        p1 = nz ? v  : p1;
        cnt += nz;
    }
}

// rare fallback: walk gmem backward from element j0 for last two nonzeros
__device__ __noinline__ void walk_back(const int* __restrict__ rowp, int j0,
                                       int& o1, int& o2)
{
    o1 = 127; o2 = 127;
    int f = 0;
    for (int j = j0; j >= 0 && f < 2; --j) {
        int v = rowp[j];
        if (v) { if (!f) o1 = v; else o2 = v; ++f; }
    }
}

__global__ void __launch_bounds__(TPB) pattern_kernel(
    const int4* __restrict__ x4, float4* __restrict__ out)
{
    const int warp = (blockIdx.x * TPB + threadIdx.x) >> 5;   // = row
    const int l    = threadIdx.x & 31;
    const long long row = warp;

    // ---- Loads: two warp-contiguous 512B regions per warp ----
    const int4* rp4 = x4 + row * (L_LEN / 4);
    int4 va = rp4[l];           // elements 4l .. 4l+3
    int4 vb = rp4[32 + l];      // elements 128+4l .. 128+4l+3

    // ---- Pack each int4 (values < 40) into 4 bytes ----
    unsigned loA = __byte_perm((unsigned)va.x, (unsigned)va.y, 0x0040);
    unsigned hiA = __byte_perm((unsigned)va.z, (unsigned)va.w, 0x0040);
    unsigned wA  = __byte_perm(loA, hiA, 0x5410);
    unsigned loB = __byte_perm((unsigned)vb.x, (unsigned)vb.y, 0x0040);
    unsigned hiB = __byte_perm((unsigned)vb.z, (unsigned)vb.w, 0x0040);
    unsigned wB  = __byte_perm(loB, hiB, 0x5410);

    // ---- Chain inits from neighbor lanes ----
    const unsigned FULL = 0xffffffffu;
    unsigned upA  = __shfl_up_sync(FULL, wA, 1);   // lane l-1's chunk-A word
    unsigned upB  = __shfl_up_sync(FULL, wB, 1);   // lane l-1's chunk-B word
    unsigned wA31 = __shfl_sync(FULL, wA, 31);     // elements 124..127

    const int* rowp = (const int*)rp4;

    int a1 = 127, a2 = 127;                        // prevs before element 4l
    if (l) {
        int p1, p2, cnt;
        last2nz_word(upA, p1, p2, cnt);
        if (cnt >= 2) { a1 = p1; a2 = p2; }
        else walk_back(rowp, 4 * l - 1, a1, a2);
    }

    int b1, b2;                                    // prevs before 128+4l
    {
        unsigned pw = l ? upB : wA31;
        int p1, p2, cnt;
        last2nz_word(pw, p1, p2, cnt);
        if (cnt >= 2) { b1 = p1; b2 = p2; }
        else walk_back(rowp, 128 + 4 * l - 1, b1, b2);
    }

    // ---- SWAR scan: low half = chunk A, high half = chunk B; 4 steps ----
    const unsigned BIAS = 0x64006400u;             // half2 {1024, 1024}
    const unsigned BMSK = 0x00FF00FFu;
    unsigned p1h = (unsigned)(0x6400 | a1) | ((unsigned)(0x6400 | b1) << 16);
    unsigned p2h = (unsigned)(0x6400 | a2) | ((unsigned)(0x6400 | b2) << 16);
    unsigned accR = 0, accI = 0, accP = 0, accN = 0;

    #pragma unroll
    for (int k = 0; k < 4; ++k) {
        unsigned pr = __byte_perm(wA, wB, 0x0400 + k * 0x0101);
        unsigned v  = (pr & BMSK) | BIAS;          // {1024+va_k, 1024+vb_k}
        unsigned mR = heq2_mask(v, p1h);
        unsigned mI = hgt2_mask(v, p1h);
        unsigned mP = heq2_mask(v, p2h);
        unsigned mN = hne2_mask(v, BIAS);
        accR = __vsub2(accR, mR);                  // mask == -1 per u16 lane
        accI = __vsub2(accI, mI);
        accP = __vsub2(accP, mP);
        accN = __vsub2(accN, mN);
        p2h = (p1h & mN) | (p2h & ~mN);            // single LOP3 each
        p1h = (v   & mN) | (p1h & ~mN);
    }

    // ---- Warp reduction: REDUX adds; u16 lane sums <= 128, no carry ----
    accR = __reduce_add_sync(FULL, accR);
    accI = __reduce_add_sync(FULL, accI);
    accP = __reduce_add_sync(FULL, accP);
    accN = __reduce_add_sync(FULL, accN);

    if (l == 0) {
        int REP = (int)(accR & 0xffffu) + (int)(accR >> 16);
        int INC = (int)(accI & 0xffffu) + (int)(accI >> 16);
        int PER = (int)(accP & 0xffffu) + (int)(accP >> 16);
        int N   = (int)(accN & 0xffffu) + (int)(accN >> 16);
        float o0 = 0.f, o1 = 0.f, o2 = 0.f, o3 = 0.f;
        if (N > 1) {
            int DEC  = (N - 1) - REP - INC;
            float d1 = 1.0f / (float)(N - 1);
            o0 = (float)REP * d1;
            o1 = (float)INC * d1;
            o2 = (float)DEC * d1;
            if (N >= 4) o3 = (float)PER / (float)(N - 2);
        }
        out[row] = make_float4(o0, o1, o2, o3);
    }
}

extern "C" void kernel_launch(void* const* d_in, const int* in_sizes, int n_in,
                              void* d_out, int out_size)
{
    const int4* x = (const int4*)d_in[0];
    float4* out   = (float4*)d_out;
    const int total_elems = in_sizes[0];          // B * L
    const int nrows = total_elems / L_LEN;        // 131072
    const int blocks = nrows / (TPB / 32);        // 16384
    pattern_kernel<<<blocks, TPB>>>(x, out);
}

// round 12
// speedup vs baseline: 1.2892x; 1.2892x over previous
#include <cuda_runtime.h>
#include <cuda_fp16.h>

// PatternDetector: B=131072 rows x L=256 int32 in [0,40). Output Bx4 f32.
//
// Stable "nonzeros-first" argsort preserves order -> all features are
// functions of consecutive-nonzero pairs -> forward scan per row.
// dec = (n-1) - rep - inc.
//
// R12: persistent blocks, 2-stage cp.async double buffer, NO repack:
// the scan reads raw int32 from smem. Tile = 8 rows (8KB raw), stored as
// 64 chunk-slots of 144B (32 elements each; pad keeps LDS.128 conflict-free:
// word = (36q + 4p) mod 32 -> lane l hits bank-group l mod 8).
// Thread t scans chunk t: chain A = elems 0-15, chain B = 16-31 of chunk,
// SIMD'd in one half2 recurrence (value = 1024+v exact; masks via
// set.*.u32.f16x2; prev blend = 1 LOP3; counters packed u16x2).
// 18.4KB smem/block -> 12 blocks/SM = 24 warps, each independently phased.

constexpr int TPB        = 64;     // threads = chunks per tile
constexpr int ROWS_TILE  = 8;
constexpr int L_LEN      = 256;
constexpr int TILE_INT4  = ROWS_TILE * L_LEN / 4;   // 512
constexpr int SLOT_B     = 144;    // bytes per 32-elem chunk slot (128 data + 16 pad)
constexpr int BUF_B      = TPB * SLOT_B;            // 9216
constexpr int GRID       = 1776;   // 148 SM x 12 blocks

__device__ __forceinline__ unsigned heq2_mask(unsigned a, unsigned b) {
    unsigned d; asm("set.eq.u32.f16x2 %0, %1, %2;" : "=r"(d) : "r"(a), "r"(b)); return d;
}
__device__ __forceinline__ unsigned hgt2_mask(unsigned a, unsigned b) {
    unsigned d; asm("set.gt.u32.f16x2 %0, %1, %2;" : "=r"(d) : "r"(a), "r"(b)); return d;
}
__device__ __forceinline__ unsigned hne2_mask(unsigned a, unsigned b) {
    unsigned d; asm("set.ne.u32.f16x2 %0, %1, %2;" : "=r"(d) : "r"(a), "r"(b)); return d;
}

// last two nonzeros among 4 ints (ascending position), count
__device__ __forceinline__ void last2nz_int4(int4 q, int& p1, int& p2, int& cnt)
{
    int vv[4] = {q.x, q.y, q.z, q.w};
    p1 = 0; p2 = 0; cnt = 0;
    #pragma unroll
    for (int k = 0; k < 4; ++k) {
        int v = vv[k];
        bool nz = (v != 0);
        p2 = nz ? p1 : p2;
        p1 = nz ? v  : p1;
        cnt += nz;
    }
}

// rare fallback: walk this row's raw ints (in slotted smem) backward from
// element j0 for the last two nonzeros. base = &buf[row's first slot].
__device__ __noinline__ void walk_back(const unsigned char* rowbase, int j0,
                                       int& o1, int& o2)
{
    o1 = 127; o2 = 127;
    int f = 0;
    for (int j = j0; j >= 0 && f < 2; --j) {
        int v = *(const int*)(rowbase + (j >> 5) * SLOT_B + (j & 31) * 4);
        if (v) { if (!f) o1 = v; else o2 = v; ++f; }
    }
}

// issue one tile (8 cp.async.cg of 16B per thread) + commit
__device__ __forceinline__ void issue_tile(const char* gsrc, unsigned smem_dst)
{
    #pragma unroll
    for (int i = 0; i < TILE_INT4 / TPB; ++i) {       // 8 per thread
        int idx = i * TPB + (int)threadIdx.x;         // int4 index in tile
        unsigned dst = smem_dst + (unsigned)(idx >> 3) * SLOT_B
                                + (unsigned)(idx & 7) * 16;
        asm volatile("cp.async.cg.shared.global [%0], [%1], 16;"
                     :: "r"(dst), "l"(gsrc + (size_t)idx * 16));
    }
    asm volatile("cp.async.commit_group;" ::: "memory");
}

__global__ void __launch_bounds__(TPB, 12) pattern_kernel(
    const int4* __restrict__ x4, float4* __restrict__ out, int total_tiles)
{
    __shared__ unsigned char smem[2 * BUF_B];         // 18432 B
    const unsigned smem_u = (unsigned)__cvta_generic_to_shared(smem);

    const int tid = threadIdx.x;
    const int cr  = tid & 7;                          // chunk within row

    int t = blockIdx.x;
    if (t < total_tiles)
        issue_tile((const char*)(x4 + (long long)t * TILE_INT4), smem_u);

    int buf = 0;
    for (; t < total_tiles; t += GRID, buf ^= 1) {
        // wait for current buffer's group (only pending one), then barrier:
        // after it, (a) buf's data is visible to all, (b) every thread has
        // finished scanning buf^1 from the previous iteration.
        asm volatile("cp.async.wait_group 0;" ::: "memory");
        __syncthreads();

        // overlap: stream next tile into the other buffer while we scan
        int tn = t + GRID;
        if (tn < total_tiles)
            issue_tile((const char*)(x4 + (long long)tn * TILE_INT4),
                       smem_u + (buf ^ 1) * BUF_B);

        const unsigned char* bufp = smem + buf * BUF_B;
        const unsigned char* slot = bufp + tid * SLOT_B;
        const unsigned char* rowbase = bufp + (tid & ~7) * SLOT_B;

        // ---- chain inits ----
        int a1 = 127, a2 = 127;                       // before chunk elem 0
        if (cr) {
            int4 q = *(const int4*)(slot - SLOT_B + 112);  // prev chunk 28..31
            int p1, p2, cnt;
            last2nz_int4(q, p1, p2, cnt);
            if (cnt >= 2) { a1 = p1; a2 = p2; }
            else walk_back(rowbase, cr * 32 - 1, a1, a2);
        }
        int b1, b2;                                   // before chunk elem 16
        {
            int4 q = *(const int4*)(slot + 48);            // own elems 12..15
            int p1, p2, cnt;
            last2nz_int4(q, p1, p2, cnt);
            if (cnt >= 2) { b1 = p1; b2 = p2; }
            else walk_back(rowbase, cr * 32 + 15, b1, b2);
        }

        // ---- SWAR scan: low half = chain A (0-15), high = B (16-31) ----
        const unsigned BIAS1 = 0x6400u;               // half 1024
        unsigned p1h = (unsigned)(BIAS1 | a1) | ((unsigned)(BIAS1 | b1) << 16);
        unsigned p2h = (unsigned)(BIAS1 | a2) | ((unsigned)(BIAS1 | b2) << 16);
        unsigned accR = 0, accI = 0, accP = 0, accN = 0;

        #pragma unroll
        for (int h = 0; h < 4; ++h) {
            int4 qa = *(const int4*)(slot + h * 16);        // elems 4h..4h+3
            int4 qb = *(const int4*)(slot + 64 + h * 16);   // elems 16+4h..
            int va[4] = {qa.x, qa.y, qa.z, qa.w};
            int vb[4] = {qb.x, qb.y, qb.z, qb.w};
            #pragma unroll
            for (int k = 0; k < 4; ++k) {
                unsigned vaa = (unsigned)va[k] | BIAS1;
                unsigned vbb = (unsigned)vb[k] | BIAS1;
                unsigned v   = vaa + (vbb << 16);     // {1024+va, 1024+vb}
                unsigned mR = heq2_mask(v, p1h);
                unsigned mI = hgt2_mask(v, p1h);
                unsigned mP = heq2_mask(v, p2h);
                unsigned mN = hne2_mask(v, 0x64006400u);
                accR = __vsub2(accR, mR);             // mask == -1 per u16
                accI = __vsub2(accI, mI);
                accP = __vsub2(accP, mP);
                accN = __vsub2(accN, mN);
                p2h = (p1h & mN) | (p2h & ~mN);       // single LOP3 each
                p1h = (v   & mN) | (p1h & ~mN);
            }
        }

        // ---- reduce the 8 chunk lanes of this row (u16 sums <=128) ----
        #pragma unroll
        for (int m = 1; m <= 4; m <<= 1) {
            accR = __vadd2(accR, __shfl_xor_sync(0xffffffffu, accR, m));
            accI = __vadd2(accI, __shfl_xor_sync(0xffffffffu, accI, m));
            accP = __vadd2(accP, __shfl_xor_sync(0xffffffffu, accP, m));
            accN = __vadd2(accN, __shfl_xor_sync(0xffffffffu, accN, m));
        }

        if (cr == 0) {
            int REP = (int)(accR & 0xffffu) + (int)(accR >> 16);
            int INC = (int)(accI & 0xffffu) + (int)(accI >> 16);
            int PER = (int)(accP & 0xffffu) + (int)(accP >> 16);
            int N   = (int)(accN & 0xffffu) + (int)(accN >> 16);
            float o0 = 0.f, o1 = 0.f, o2 = 0.f, o3 = 0.f;
            if (N > 1) {
                int DEC  = (N - 1) - REP - INC;
                float d1 = 1.0f / (float)(N - 1);
                o0 = (float)REP * d1;
                o1 = (float)INC * d1;
                o2 = (float)DEC * d1;
                if (N >= 4) o3 = (float)PER / (float)(N - 2);
            }
            out[(long long)t * ROWS_TILE + (tid >> 3)] =
                make_float4(o0, o1, o2, o3);
        }
    }
}

extern "C" void kernel_launch(void* const* d_in, const int* in_sizes, int n_in,
                              void* d_out, int out_size)
{
    const int4* x = (const int4*)d_in[0];
    float4* out   = (float4*)d_out;
    const int total_elems = in_sizes[0];              // B * L
    const int nrows       = total_elems / L_LEN;      // 131072
    const int total_tiles = nrows / ROWS_TILE;        // 16384
    const int grid = (total_tiles < GRID) ? total_tiles : GRID;
    pattern_kernel<<<grid, TPB>>>(x, out, total_tiles);
}

// round 13
// speedup vs baseline: 1.2906x; 1.0011x over previous
#include <cuda_runtime.h>
#include <cuda_fp16.h>

// PatternDetector: B=131072 rows x L=256 int32 in [0,40). Output Bx4 f32.
//
// Stable "nonzeros-first" argsort preserves order -> all features are
// functions of consecutive-nonzero pairs -> forward scan per row.
// dec = (n-1) - rep - inc.
//
// R13 = R12 scan/init (no repack; raw int32 in 144B-padded chunk slots,
// conflict-free LDS.128; SWAR half2 scan: value = 1024+v exact; masks via
// set.*.u32.f16x2; prev blend = 1 LOP3; counters packed u16x2)
//      + R10 tile size (16 rows) and TPB=128:
// 2-stage cp.async double buffer, 36.9KB smem -> 6 blocks/SM = 24 warps,
// half of R12's per-byte barrier overhead, no repack phase.

constexpr int TPB        = 128;    // threads = chunks per tile
constexpr int ROWS_TILE  = 16;
constexpr int L_LEN      = 256;
constexpr int TILE_INT4  = ROWS_TILE * L_LEN / 4;   // 1024
constexpr int SLOT_B     = 144;    // 32-elem chunk slot (128 data + 16 pad)
constexpr int BUF_B      = TPB * SLOT_B;            // 18432
constexpr int GRID       = 888;    // 148 SM x 6 blocks

__device__ __forceinline__ unsigned heq2_mask(unsigned a, unsigned b) {
    unsigned d; asm("set.eq.u32.f16x2 %0, %1, %2;" : "=r"(d) : "r"(a), "r"(b)); return d;
}
__device__ __forceinline__ unsigned hgt2_mask(unsigned a, unsigned b) {
    unsigned d; asm("set.gt.u32.f16x2 %0, %1, %2;" : "=r"(d) : "r"(a), "r"(b)); return d;
}
__device__ __forceinline__ unsigned hne2_mask(unsigned a, unsigned b) {
    unsigned d; asm("set.ne.u32.f16x2 %0, %1, %2;" : "=r"(d) : "r"(a), "r"(b)); return d;
}

// last two nonzeros among 4 ints (ascending position), count
__device__ __forceinline__ void last2nz_int4(int4 q, int& p1, int& p2, int& cnt)
{
    int vv[4] = {q.x, q.y, q.z, q.w};
    p1 = 0; p2 = 0; cnt = 0;
    #pragma unroll
    for (int k = 0; k < 4; ++k) {
        int v = vv[k];
        bool nz = (v != 0);
        p2 = nz ? p1 : p2;
        p1 = nz ? v  : p1;
        cnt += nz;
    }
}

// rare fallback: walk this row's ints (slotted smem) backward from elem j0
__device__ __noinline__ void walk_back(const unsigned char* rowbase, int j0,
                                       int& o1, int& o2)
{
    o1 = 127; o2 = 127;
    int f = 0;
    for (int j = j0; j >= 0 && f < 2; --j) {
        int v = *(const int*)(rowbase + (j >> 5) * SLOT_B + (j & 31) * 4);
        if (v) { if (!f) o1 = v; else o2 = v; ++f; }
    }
}

// issue one tile (8 cp.async.cg of 16B per thread) + commit
__device__ __forceinline__ void issue_tile(const char* gsrc, unsigned smem_dst)
{
    #pragma unroll
    for (int i = 0; i < TILE_INT4 / TPB; ++i) {       // 8 per thread
        int idx = i * TPB + (int)threadIdx.x;         // int4 index in tile
        unsigned dst = smem_dst + (unsigned)(idx >> 3) * SLOT_B
                                + (unsigned)(idx & 7) * 16;
        asm volatile("cp.async.cg.shared.global [%0], [%1], 16;"
                     :: "r"(dst), "l"(gsrc + (size_t)idx * 16));
    }
    asm volatile("cp.async.commit_group;" ::: "memory");
}

__global__ void __launch_bounds__(TPB, 6) pattern_kernel(
    const int4* __restrict__ x4, float4* __restrict__ out, int total_tiles)
{
    __shared__ unsigned char smem[2 * BUF_B];         // 36864 B
    const unsigned smem_u = (unsigned)__cvta_generic_to_shared(smem);

    const int tid = threadIdx.x;
    const int cr  = tid & 7;                          // chunk within row

    int t = blockIdx.x;
    if (t < total_tiles)
        issue_tile((const char*)(x4 + (long long)t * TILE_INT4), smem_u);

    int buf = 0;
    for (; t < total_tiles; t += GRID, buf ^= 1) {
        // wait for current buffer's copy; barrier also proves every thread
        // finished scanning buf^1 last iteration (safe to refill it).
        asm volatile("cp.async.wait_group 0;" ::: "memory");
        __syncthreads();

        int tn = t + GRID;
        if (tn < total_tiles)
            issue_tile((const char*)(x4 + (long long)tn * TILE_INT4),
                       smem_u + (buf ^ 1) * BUF_B);

        const unsigned char* bufp    = smem + buf * BUF_B;
        const unsigned char* slot    = bufp + tid * SLOT_B;
        const unsigned char* rowbase = bufp + (tid & ~7) * SLOT_B;

        // ---- chain inits ----
        int a1 = 127, a2 = 127;                       // before chunk elem 0
        if (cr) {
            int4 q = *(const int4*)(slot - SLOT_B + 112);  // prev chunk 28..31
            int p1, p2, cnt;
            last2nz_int4(q, p1, p2, cnt);
            if (cnt >= 2) { a1 = p1; a2 = p2; }
            else walk_back(rowbase, cr * 32 - 1, a1, a2);
        }
        int b1, b2;                                   // before chunk elem 16
        {
            int4 q = *(const int4*)(slot + 48);            // own elems 12..15
            int p1, p2, cnt;
            last2nz_int4(q, p1, p2, cnt);
            if (cnt >= 2) { b1 = p1; b2 = p2; }
            else walk_back(rowbase, cr * 32 + 15, b1, b2);
        }

        // ---- SWAR scan: low half = chain A (0-15), high = B (16-31) ----
        const unsigned BIAS1 = 0x6400u;               // half 1024
        unsigned p1h = (unsigned)(BIAS1 | a1) | ((unsigned)(BIAS1 | b1) << 16);
        unsigned p2h = (unsigned)(BIAS1 | a2) | ((unsigned)(BIAS1 | b2) << 16);
        unsigned accR = 0, accI = 0, accP = 0, accN = 0;

        #pragma unroll
        for (int h = 0; h < 4; ++h) {
            int4 qa = *(const int4*)(slot + h * 16);        // elems 4h..4h+3
            int4 qb = *(const int4*)(slot + 64 + h * 16);   // elems 16+4h..
            int va[4] = {qa.x, qa.y, qa.z, qa.w};
            int vb[4] = {qb.x, qb.y, qb.z, qb.w};
            #pragma unroll
            for (int k = 0; k < 4; ++k) {
                unsigned vaa = (unsigned)va[k] | BIAS1;
                unsigned vbb = (unsigned)vb[k] | BIAS1;
                unsigned v   = vaa + (vbb << 16);     // {1024+va, 1024+vb}
                unsigned mR = heq2_mask(v, p1h);
                unsigned mI = hgt2_mask(v, p1h);
                unsigned mP = heq2_mask(v, p2h);
                unsigned mN = hne2_mask(v, 0x64006400u);
                accR = __vsub2(accR, mR);             // mask == -1 per u16
                accI = __vsub2(accI, mI);
                accP = __vsub2(accP, mP);
                accN = __vsub2(accN, mN);
                p2h = (p1h & mN) | (p2h & ~mN);       // single LOP3 each
                p1h = (v   & mN) | (p1h & ~mN);
            }
        }

        // ---- reduce the 8 chunk lanes of this row (u16 sums <= 128) ----
        #pragma unroll
        for (int m = 1; m <= 4; m <<= 1) {
            accR = __vadd2(accR, __shfl_xor_sync(0xffffffffu, accR, m));
            accI = __vadd2(accI, __shfl_xor_sync(0xffffffffu, accI, m));
            accP = __vadd2(accP, __shfl_xor_sync(0xffffffffu, accP, m));
            accN = __vadd2(accN, __shfl_xor_sync(0xffffffffu, accN, m));
        }

        if (cr == 0) {
            int REP = (int)(accR & 0xffffu) + (int)(accR >> 16);
            int INC = (int)(accI & 0xffffu) + (int)(accI >> 16);
            int PER = (int)(accP & 0xffffu) + (int)(accP >> 16);
            int N   = (int)(accN & 0xffffu) + (int)(accN >> 16);
            float o0 = 0.f, o1 = 0.f, o2 = 0.f, o3 = 0.f;
            if (N > 1) {
                int DEC  = (N - 1) - REP - INC;
                float d1 = 1.0f / (float)(N - 1);
                o0 = (float)REP * d1;
                o1 = (float)INC * d1;
                o2 = (float)DEC * d1;
                if (N >= 4) o3 = (float)PER / (float)(N - 2);
            }
            out[(long long)t * ROWS_TILE + (tid >> 3)] =
                make_float4(o0, o1, o2, o3);
        }
    }
}

extern "C" void kernel_launch(void* const* d_in, const int* in_sizes, int n_in,
                              void* d_out, int out_size)
{
    const int4* x = (const int4*)d_in[0];
    float4* out   = (float4*)d_out;
    const int total_elems = in_sizes[0];              // B * L
    const int nrows       = total_elems / L_LEN;      // 131072
    const int total_tiles = nrows / ROWS_TILE;        // 8192
    const int grid = (total_tiles < GRID) ? total_tiles : GRID;
    pattern_kernel<<<grid, TPB>>>(x, out, total_tiles);
}